// round 16
// baseline (speedup 1.0000x reference)
#include <cuda_runtime.h>
#include <cuda_bf16.h>
#include <math.h>
#include <stdint.h>

#define NN 10000
#define NE 320000
#define H  256

// ---------------- scratch ----------------
__device__ float g_Pa[NN * H];
__device__ float g_Pb[NN * H];
__device__ float g_agg2[2 * NN * H];
__device__ float g_q[NN * H];
__device__ float g_h1[NN * H];
__device__ float g_aggx[NN * 3];
__device__ int   g_deg[NN];
__device__ int   g_cur[NN];
__device__ int   g_srow[NE];
__device__ int   g_scol[NE];
__device__ float2 g_sea[NE];
__device__ unsigned g_WF[15 * 32768];

__device__ __forceinline__ float tanhap(float v) {
    float t;
    asm("tanh.approx.f32 %0, %1;" : "=f"(t) : "f"(v));
    return t;
}
__device__ __forceinline__ float siluf(float v) {
    return 0.5f * v * tanhap(0.5f * v) + 0.5f * v;
}
__device__ __forceinline__ float sigmf(float v) {
    return 0.5f * tanhap(0.5f * v) + 0.5f;
}
__device__ __forceinline__ uint32_t pack2(float x, float y) {
    __nv_bfloat162 t = __floats2bfloat162_rn(x, y);
    return *(uint32_t*)&t;
}
__device__ __forceinline__ float2 up2(uint32_t v) {
    return __bfloat1622float2(*(__nv_bfloat162*)&v);
}
__device__ __forceinline__ void mma_bf16(float c[4], uint32_t a0, uint32_t a1, uint32_t a2,
                                         uint32_t a3, uint32_t b0, uint32_t b1) {
    asm volatile(
        "mma.sync.aligned.m16n8k16.row.col.f32.bf16.bf16.f32 "
        "{%0,%1,%2,%3}, {%4,%5,%6,%7}, {%8,%9}, {%0,%1,%2,%3};"
        : "+f"(c[0]), "+f"(c[1]), "+f"(c[2]), "+f"(c[3])
        : "r"(a0), "r"(a1), "r"(a2), "r"(a3), "r"(b0), "r"(b1));
}

// ================= prep =================
struct WPtrs { const float* w[15]; };
__global__ void combo_prep(WPtrs ptrs, const int* __restrict__ ei) {
    int i = blockIdx.x * 256 + threadIdx.x;
    int m = i >> 15;
    int j = i & 32767;
    const float* W = ptrs.w[m];
    int r = j & 1, q = (j >> 1) & 1, lane = (j >> 2) & 31, ntp = (j >> 7) & 15, kstep = j >> 11;
    int nt = ntp * 2 + q;
    int g = lane >> 2, tig = lane & 3;
    int k = kstep * 16 + 2 * tig + 8 * r;
    int n = nt * 8 + g;
    g_WF[m * 32768 + j] = pack2(W[k * H + n], W[(k + 1) * H + n]);
    if (i < NE) atomicAdd(&g_deg[ei[i]], 1);
    for (int z = i; z < 2 * NN * H; z += 1920 * 256) g_agg2[z] = 0.f;
    if (i < NN * 3) g_aggx[i] = 0.f;
}
__global__ void scan_kernel() {
    __shared__ int part[256];
    int t = threadIdx.x;
    int base = t * 40;
    int s = 0;
    for (int j = 0; j < 40; ++j) {
        int i = base + j;
        if (i < NN) s += g_deg[i];
    }
    part[t] = s;
    __syncthreads();
    if (t == 0) {
        int run = 0;
        for (int i = 0; i < 256; ++i) { int v = part[i]; part[i] = run; run += v; }
    }
    __syncthreads();
    int run = part[t];
    for (int j = 0; j < 40; ++j) {
        int i = base + j;
        if (i < NN) { g_cur[i] = run; run += g_deg[i]; g_deg[i] = 0; }
    }
}
__global__ void scatter_kernel(const int* __restrict__ ei, const float* __restrict__ ea) {
    int e = blockIdx.x * 256 + threadIdx.x;
    if (e >= NE) return;
    int r = ei[e];
    int pos = atomicAdd(&g_cur[r], 1);
    g_srow[pos] = r;
    g_scol[pos] = ei[NE + e];
    g_sea[pos] = ((const float2*)ea)[e];
}

// ================= node-side mma core: 16 rows x 32 cols per warp, quarter-N blocks =================
// Block = 64 rows x 64 cols; 8 warps = 4 row-groups x 2 col-32s. acc[4][4].
__device__ __forceinline__ void mma_block_quarter(const uint32_t* u_s, const uint4* __restrict__ Bf4,
                                                  int r0, int ntp0, int lane, float acc[4][4]) {
    int g = lane >> 2, tig = lane & 3;
    const uint32_t* ua0 = u_s + (r0 + g) * 132 + tig;
#pragma unroll
    for (int kstep = 0; kstep < 16; ++kstep) {
        uint32_t a0 = ua0[kstep * 8];
        uint32_t a1 = ua0[kstep * 8 + 8 * 132];
        uint32_t a2 = ua0[kstep * 8 + 4];
        uint32_t a3 = ua0[kstep * 8 + 8 * 132 + 4];
        const uint4* bp = Bf4 + (size_t)kstep * 512 + ntp0 * 32 + lane;
#pragma unroll
        for (int p = 0; p < 2; ++p) {
            uint4 b = __ldg(bp + p * 32);
            mma_bf16(acc[2 * p],     a0, a1, a2, a3, b.x, b.y);
            mma_bf16(acc[2 * p + 1], a0, a1, a2, a3, b.z, b.w);
        }
    }
}

// ================= node GEMM (quarter-N: gridDim.x = 4 * ceil(M/64)) =================
__global__ __launch_bounds__(256, 4) void node_mma(
    const float* __restrict__ A1, const uint4* __restrict__ B1f,
    const float* __restrict__ A2, const uint4* __restrict__ B2f,
    const float* __restrict__ bias, const float* __restrict__ resid,
    float* __restrict__ C, int M, int act) {
    __shared__ uint32_t u_s[64 * 132];
    int tid = threadIdx.x, wid = tid >> 5, lane = tid & 31;
    int m0 = (blockIdx.x >> 2) * 64;
    int bq = blockIdx.x & 3;                  // block col-quarter (64 cols)
    int r0 = (wid >> 1) * 16;
    int ntp0 = bq * 4 + (wid & 1) * 2;        // uint4 nt-pair base (2 ntp = 32 cols)

    float acc[4][4] = {};
    int npass = A2 ? 2 : 1;
    for (int pass = 0; pass < npass; ++pass) {
        const float* A = pass ? A2 : A1;
        const uint4* Bf = pass ? B2f : B1f;
        __syncthreads();
#pragma unroll 4
        for (int it = 0; it < 16; ++it) {
            int idx = it * 256 + tid;
            int e = idx >> 6;
            int kq = (idx & 63) << 2;
            int row = min(m0 + e, M - 1);
            float4 v = *(const float4*)&A[(size_t)row * H + kq];
            uint2 w;
            w.x = pack2(v.x, v.y);
            w.y = pack2(v.z, v.w);
            *(uint2*)&u_s[e * 132 + (kq >> 1)] = w;
        }
        __syncthreads();
        mma_block_quarter(u_s, Bf, r0, ntp0, lane, acc);
    }

    int g = lane >> 2, tig = lane & 3;
    int row0 = m0 + r0 + g, row1 = row0 + 8;
#pragma unroll
    for (int j = 0; j < 4; ++j) {
        int col = (ntp0 * 2 + j) * 8 + 2 * tig;
        float b0v = 0.f, b1v = 0.f;
        if (bias) { b0v = bias[col]; b1v = bias[col + 1]; }
        float v00 = acc[j][0] + b0v, v01 = acc[j][1] + b1v;
        float v10 = acc[j][2] + b0v, v11 = acc[j][3] + b1v;
        if (act) { v00 = siluf(v00); v01 = siluf(v01); v10 = siluf(v10); v11 = siluf(v11); }
        if (row0 < M) {
            if (resid) {
                float2 rv = *(const float2*)&resid[(size_t)row0 * H + col];
                v00 += rv.x; v01 += rv.y;
            }
            *(float2*)&C[(size_t)row0 * H + col] = make_float2(v00, v01);
        }
        if (row1 < M) {
            if (resid) {
                float2 rv = *(const float2*)&resid[(size_t)row1 * H + col];
                v10 += rv.x; v11 += rv.y;
            }
            *(float2*)&C[(size_t)row1 * H + col] = make_float2(v10, v11);
        }
    }
}

// ================= dual projection (quarter-N) =================
__global__ __launch_bounds__(256, 4) void dual_proj(
    const float* __restrict__ A, const uint4* __restrict__ B1f, const uint4* __restrict__ B2f,
    float* __restrict__ O1, float* __restrict__ O2, int M) {
    __shared__ uint32_t u_s[64 * 132];
    int tid = threadIdx.x, wid = tid >> 5, lane = tid & 31;
    int m0 = (blockIdx.x >> 2) * 64;
    int bq = blockIdx.x & 3;
    int r0 = (wid >> 1) * 16;
    int ntp0 = bq * 4 + (wid & 1) * 2;
    int g = lane >> 2, tig = lane & 3;

#pragma unroll 4
    for (int it = 0; it < 16; ++it) {
        int idx = it * 256 + tid;
        int e = idx >> 6;
        int kq = (idx & 63) << 2;
        int row = min(m0 + e, M - 1);
        float4 v = *(const float4*)&A[(size_t)row * H + kq];
        uint2 w;
        w.x = pack2(v.x, v.y);
        w.y = pack2(v.z, v.w);
        *(uint2*)&u_s[e * 132 + (kq >> 1)] = w;
    }
    __syncthreads();

    int row0 = m0 + r0 + g, row1 = row0 + 8;
#pragma unroll
    for (int pass = 0; pass < 2; ++pass) {
        const uint4* Bf = pass ? B2f : B1f;
        float* O = pass ? O2 : O1;
        float acc[4][4] = {};
        mma_block_quarter(u_s, Bf, r0, ntp0, lane, acc);
#pragma unroll
        for (int j = 0; j < 4; ++j) {
            int col = (ntp0 * 2 + j) * 8 + 2 * tig;
            if (row0 < M) *(float2*)&O[(size_t)row0 * H + col] = make_float2(acc[j][0], acc[j][1]);
            if (row1 < M) *(float2*)&O[(size_t)row1 * H + col] = make_float2(acc[j][2], acc[j][3]);
        }
    }
}

// ================= edge kernel: R14 structure, now 3 CTAs/SM =================
// smem (u32 units)
#define EU   0
#define EPS  8448
#define EATT 8512
#define EB2  8576
#define EWV  8832
#define ESR  9088
#define ESC  9152
#define EEA  9216
#define ETOT 9344
#define EDGE_SMEM (ETOT * 4)

template <bool COORD>
__global__ __launch_bounds__(256, 3) void edge_bf16_kernel(
    const float* __restrict__ Pa, const float* __restrict__ Pb,
    const float* __restrict__ wtail, const float* __restrict__ b1,
    const uint4* __restrict__ W2F, const float* __restrict__ b2,
    const float* __restrict__ wv, const float* __restrict__ ab,
    float* __restrict__ agg, const float* __restrict__ xg) {
    extern __shared__ uint32_t sm32[];
    float* ps    = (float*)(sm32 + EPS);
    float* att_s = (float*)(sm32 + EATT);
    float* b2s   = (float*)(sm32 + EB2);
    float* wvs   = (float*)(sm32 + EWV);
    int* srow_s  = (int*)(sm32 + ESR);
    int* scol_s  = (int*)(sm32 + ESC);
    float* eas   = (float*)(sm32 + EEA);

    int tid = threadIdx.x, wid = tid >> 5, lane = tid & 31;
    int g = lane >> 2, tig = lane & 3;
    int e0 = blockIdx.x * 64;
    int rg = wid >> 2;
    int cq = wid & 3;

    if (tid < 64) {
        srow_s[tid] = g_srow[e0 + tid];
        scol_s[tid] = g_scol[e0 + tid];
        float2 a = g_sea[e0 + tid];
        eas[tid] = a.x;
        eas[64 + tid] = a.y;
        ps[tid] = 0.f;
    }
    b2s[tid] = b2[tid];
    wvs[tid] = wv[tid];

    int kq = (tid & 63) << 2;
    float4 w0 = *(const float4*)&wtail[kq];
    float4 w1 = *(const float4*)&wtail[H + kq];
    float4 bv = *(const float4*)&b1[kq];
    __syncthreads();

    int esub = tid >> 6;
#pragma unroll 4
    for (int it = 0; it < 16; ++it) {
        int e = it * 4 + esub;
        int r = srow_s[e], cl = scol_s[e];
        float4 pa = *(const float4*)&Pa[(size_t)r * H + kq];
        float4 pb = *(const float4*)&Pb[(size_t)cl * H + kq];
        float a0 = eas[e], a1 = eas[64 + e];
        float t0 = siluf(pa.x + pb.x + a0 * w0.x + a1 * w1.x + bv.x);
        float t1 = siluf(pa.y + pb.y + a0 * w0.y + a1 * w1.y + bv.y);
        float t2 = siluf(pa.z + pb.z + a0 * w0.z + a1 * w1.z + bv.z);
        float t3 = siluf(pa.w + pb.w + a0 * w0.w + a1 * w1.w + bv.w);
        uint2 w;
        w.x = pack2(t0, t1);
        w.y = pack2(t2, t3);
        *(uint2*)&sm32[EU + e * 132 + (kq >> 1)] = w;
    }
    __syncthreads();

    float acc[2][8][4] = {};
    {
        const uint32_t* ua_base = sm32 + EU + (rg * 32 + g) * 132 + tig;
#pragma unroll
        for (int kstep = 0; kstep < 16; ++kstep) {
            uint32_t a[2][4];
#pragma unroll
            for (int s = 0; s < 2; ++s) {
                const uint32_t* ua = ua_base + s * 16 * 132 + kstep * 8;
                a[s][0] = ua[0];
                a[s][1] = ua[8 * 132];
                a[s][2] = ua[4];
                a[s][3] = ua[8 * 132 + 4];
            }
            const uint4* bp = W2F + (size_t)kstep * 512 + cq * 128 + lane;
#pragma unroll
            for (int p = 0; p < 4; ++p) {
                uint4 b = __ldg(bp + p * 32);
#pragma unroll
                for (int s = 0; s < 2; ++s) {
                    mma_bf16(acc[s][2 * p],     a[s][0], a[s][1], a[s][2], a[s][3], b.x, b.y);
                    mma_bf16(acc[s][2 * p + 1], a[s][0], a[s][1], a[s][2], a[s][3], b.z, b.w);
                }
            }
        }
    }
    __syncthreads();

#pragma unroll
    for (int s = 0; s < 2; ++s) {
        int row0 = rg * 32 + s * 16 + g, row1 = row0 + 8;
        float p0 = 0.f, p1 = 0.f;
#pragma unroll
        for (int nt = 0; nt < 8; ++nt) {
            int col = cq * 64 + nt * 8 + 2 * tig;
            float bb0 = b2s[col], bb1 = b2s[col + 1];
            float wc0 = wvs[col], wc1 = wvs[col + 1];
            float v00 = siluf(acc[s][nt][0] + bb0), v01 = siluf(acc[s][nt][1] + bb1);
            float v10 = siluf(acc[s][nt][2] + bb0), v11 = siluf(acc[s][nt][3] + bb1);
            if (!COORD) {
                sm32[EU + row0 * 132 + (cq * 8 + nt) * 4 + tig] = pack2(v00, v01);
                sm32[EU + row1 * 132 + (cq * 8 + nt) * 4 + tig] = pack2(v10, v11);
            }
            p0 += v00 * wc0 + v01 * wc1;
            p1 += v10 * wc0 + v11 * wc1;
        }
        atomicAdd(&ps[row0], p0);
        atomicAdd(&ps[row1], p1);
    }
    __syncthreads();

    if (COORD) {
        if (tid < 64) {
            float phi = ps[tid] * 0.01f;
            int r = srow_s[tid], c = scol_s[tid];
            float dx = xg[r * 3 + 0] - xg[c * 3 + 0];
            float dy = xg[r * 3 + 1] - xg[c * 3 + 1];
            float dz = xg[r * 3 + 2] - xg[c * 3 + 2];
            float inv = 1.0f / (sqrtf(dx * dx + dy * dy + dz * dz + 1e-8f) + 1.0f);
            atomicAdd(&agg[(size_t)r * 3 + 0], dx * inv * phi);
            atomicAdd(&agg[(size_t)r * 3 + 1], dy * inv * phi);
            atomicAdd(&agg[(size_t)r * 3 + 2], dz * inv * phi);
        }
    } else {
        if (tid < 64) att_s[tid] = sigmf(ps[tid] + ab[0]) * 0.01f;
        __syncthreads();
        int cch = tid & 31;
        int s0 = (tid >> 5) * 8;
        float av[8] = {};
        int currow = srow_s[s0];
        for (int s = s0; s < s0 + 8; ++s) {
            int r = srow_s[s];
            if (r != currow) {
                float* dst = agg + (size_t)currow * H + cch * 8;
#pragma unroll
                for (int j = 0; j < 8; ++j) { atomicAdd(dst + j, av[j]); av[j] = 0.f; }
                currow = r;
            }
            float a = att_s[s];
            uint4 w4 = *(const uint4*)(sm32 + EU + s * 132 + cch * 4);
            float2 f;
            f = up2(w4.x); av[0] += f.x * a; av[1] += f.y * a;
            f = up2(w4.y); av[2] += f.x * a; av[3] += f.y * a;
            f = up2(w4.z); av[4] += f.x * a; av[5] += f.y * a;
            f = up2(w4.w); av[6] += f.x * a; av[7] += f.y * a;
        }
        float* dst = agg + (size_t)currow * H + cch * 8;
#pragma unroll
        for (int j = 0; j < 8; ++j) atomicAdd(dst + j, av[j]);
    }
}

__global__ void x_final_kernel(const float* __restrict__ x, const float* __restrict__ aggx,
                               float* __restrict__ out) {
    int i = blockIdx.x * blockDim.x + threadIdx.x;
    if (i < NN * 3) out[i] = x[i] + aggx[i];
}

// ================= launch =================
extern "C" void kernel_launch(void* const* d_in, const int* in_sizes, int n_in,
                              void* d_out, int out_size) {
    const float* h0 = (const float*)d_in[0];
    const float* x = (const float*)d_in[1];
    const int* ei = (const int*)d_in[2];
    const float* ea = (const float*)d_in[3];
    const float* p[2][10];
    for (int l = 0; l < 2; ++l)
        for (int i = 0; i < 10; ++i) p[l][i] = (const float*)d_in[4 + l * 10 + i];
    // p[l]: 0 ew1, 1 eb1, 2 ew2, 3 eb2, 4 nw1, 5 nb1, 6 nw2, 7 nb2, 8 aw, 9 ab
    const float* cw1 = (const float*)d_in[24];
    const float* cb1 = (const float*)d_in[25];
    const float* cw2 = (const float*)d_in[26];
    const float* cb2 = (const float*)d_in[27];
    const float* cw3 = (const float*)d_in[28];

    float* outh = (float*)d_out;
    float* outx = outh + (size_t)NN * H;

    float *Pa, *Pb, *agg2, *q, *h1, *aggx;
    unsigned* wf;
    cudaGetSymbolAddress((void**)&Pa, g_Pa);
    cudaGetSymbolAddress((void**)&Pb, g_Pb);
    cudaGetSymbolAddress((void**)&agg2, g_agg2);
    cudaGetSymbolAddress((void**)&q, g_q);
    cudaGetSymbolAddress((void**)&h1, g_h1);
    cudaGetSymbolAddress((void**)&aggx, g_aggx);
    cudaGetSymbolAddress((void**)&wf, g_WF);

    cudaFuncSetAttribute(edge_bf16_kernel<false>, cudaFuncAttributeMaxDynamicSharedMemorySize, EDGE_SMEM);
    cudaFuncSetAttribute(edge_bf16_kernel<true>, cudaFuncAttributeMaxDynamicSharedMemorySize, EDGE_SMEM);

    int gnode = 4 * ((NN + 63) / 64);   // quarter-N: 4 blocks per 64-row tile

    WPtrs wp;
    for (int l = 0; l < 2; ++l) {
        wp.w[l * 6 + 0] = p[l][0];
        wp.w[l * 6 + 1] = p[l][0] + 256 * H;
        wp.w[l * 6 + 2] = p[l][2];
        wp.w[l * 6 + 3] = p[l][4];
        wp.w[l * 6 + 4] = p[l][4] + 256 * H;
        wp.w[l * 6 + 5] = p[l][6];
    }
    wp.w[12] = cw1;
    wp.w[13] = cw1 + 256 * H;
    wp.w[14] = cw2;
    combo_prep<<<1920, 256>>>(wp, ei);
    scan_kernel<<<1, 256>>>();
    scatter_kernel<<<(NE + 255) / 256, 256>>>(ei, ea);

    const uint4* WF = (const uint4*)wf;
#define WFM(m) (WF + (size_t)(m) * 8192)

    const float* hcur = h0;
    float* houts[2] = {h1, outh};
    for (int l = 0; l < 2; ++l) {
        float* agg = agg2 + (size_t)l * NN * H;
        dual_proj<<<gnode, 256>>>(hcur, WFM(l * 6 + 0), WFM(l * 6 + 1), Pa, Pb, NN);
        edge_bf16_kernel<false><<<NE / 64, 256, EDGE_SMEM>>>(
            Pa, Pb, p[l][0] + 512 * H, p[l][1], WFM(l * 6 + 2), p[l][3], p[l][8], p[l][9],
            agg, nullptr);
        node_mma<<<gnode, 256>>>(hcur, WFM(l * 6 + 3), agg, WFM(l * 6 + 4),
                                 p[l][5], nullptr, q, NN, 1);
        node_mma<<<gnode, 256>>>(q, WFM(l * 6 + 5), nullptr, nullptr,
                                 p[l][7], hcur, houts[l], NN, 0);
        hcur = houts[l];
    }

    dual_proj<<<gnode, 256>>>(hcur, WFM(12), WFM(13), Pa, Pb, NN);
    edge_bf16_kernel<true><<<NE / 64, 256, EDGE_SMEM>>>(
        Pa, Pb, cw1 + 512 * H, cb1, WFM(14), cb2, cw3, nullptr, aggx, x);
    x_final_kernel<<<(NN * 3 + 255) / 256, 256>>>(x, aggx, outx);
}

// round 17
// speedup vs baseline: 1.7947x; 1.7947x over previous
#include <cuda_runtime.h>
#include <cuda_bf16.h>
#include <math.h>
#include <stdint.h>

#define NN 10000
#define NE 320000
#define H  256

// ---------------- scratch ----------------
__device__ float g_Pa[NN * H];
__device__ float g_Pb[NN * H];
__device__ float g_agg2[2 * NN * H];
__device__ float g_q[NN * H];
__device__ float g_h1[NN * H];
__device__ float g_aggx[NN * 3];
__device__ int   g_deg[NN];
__device__ int   g_cur[NN];
__device__ int   g_srow[NE];
__device__ int   g_scol[NE];
__device__ float2 g_sea[NE];
__device__ unsigned g_WF[15 * 32768];

__device__ __forceinline__ float tanhap(float v) {
    float t;
    asm("tanh.approx.f32 %0, %1;" : "=f"(t) : "f"(v));
    return t;
}
__device__ __forceinline__ float siluf(float v) {
    return 0.5f * v * tanhap(0.5f * v) + 0.5f * v;
}
__device__ __forceinline__ float sigmf(float v) {
    return 0.5f * tanhap(0.5f * v) + 0.5f;
}
__device__ __forceinline__ uint32_t pack2(float x, float y) {
    __nv_bfloat162 t = __floats2bfloat162_rn(x, y);
    return *(uint32_t*)&t;
}
__device__ __forceinline__ float2 up2(uint32_t v) {
    return __bfloat1622float2(*(__nv_bfloat162*)&v);
}
__device__ __forceinline__ void mma_bf16(float c[4], uint32_t a0, uint32_t a1, uint32_t a2,
                                         uint32_t a3, uint32_t b0, uint32_t b1) {
    asm volatile(
        "mma.sync.aligned.m16n8k16.row.col.f32.bf16.bf16.f32 "
        "{%0,%1,%2,%3}, {%4,%5,%6,%7}, {%8,%9}, {%0,%1,%2,%3};"
        : "+f"(c[0]), "+f"(c[1]), "+f"(c[2]), "+f"(c[3])
        : "r"(a0), "r"(a1), "r"(a2), "r"(a3), "r"(b0), "r"(b1));
}
// vectorized global float reduction (sm_90+): 4 floats in one RED
__device__ __forceinline__ void red_add_v4(float* p, float x, float y, float z, float w) {
    asm volatile("red.global.add.v4.f32 [%0], {%1, %2, %3, %4};"
                 :: "l"(p), "f"(x), "f"(y), "f"(z), "f"(w) : "memory");
}

// ================= prep =================
struct WPtrs { const float* w[15]; };
__global__ void combo_prep(WPtrs ptrs, const int* __restrict__ ei) {
    int i = blockIdx.x * 256 + threadIdx.x;
    int m = i >> 15;
    int j = i & 32767;
    const float* W = ptrs.w[m];
    int r = j & 1, q = (j >> 1) & 1, lane = (j >> 2) & 31, ntp = (j >> 7) & 15, kstep = j >> 11;
    int nt = ntp * 2 + q;
    int g = lane >> 2, tig = lane & 3;
    int k = kstep * 16 + 2 * tig + 8 * r;
    int n = nt * 8 + g;
    g_WF[m * 32768 + j] = pack2(W[k * H + n], W[(k + 1) * H + n]);
    if (i < NE) atomicAdd(&g_deg[ei[i]], 1);
    for (int z = i; z < 2 * NN * H; z += 1920 * 256) g_agg2[z] = 0.f;
    if (i < NN * 3) g_aggx[i] = 0.f;
}
__global__ void scan_kernel() {
    __shared__ int part[256];
    int t = threadIdx.x;
    int base = t * 40;
    int s = 0;
    for (int j = 0; j < 40; ++j) {
        int i = base + j;
        if (i < NN) s += g_deg[i];
    }
    part[t] = s;
    __syncthreads();
    if (t == 0) {
        int run = 0;
        for (int i = 0; i < 256; ++i) { int v = part[i]; part[i] = run; run += v; }
    }
    __syncthreads();
    int run = part[t];
    for (int j = 0; j < 40; ++j) {
        int i = base + j;
        if (i < NN) { g_cur[i] = run; run += g_deg[i]; g_deg[i] = 0; }
    }
}
__global__ void scatter_kernel(const int* __restrict__ ei, const float* __restrict__ ea) {
    int e = blockIdx.x * 256 + threadIdx.x;
    if (e >= NE) return;
    int r = ei[e];
    int pos = atomicAdd(&g_cur[r], 1);
    g_srow[pos] = r;
    g_scol[pos] = ei[NE + e];
    g_sea[pos] = ((const float2*)ea)[e];
}

// ================= node-side mma core: 16 rows x 64 cols per warp, split-N blocks =================
__device__ __forceinline__ void mma_block_half(const uint32_t* u_s, const uint4* __restrict__ Bf4,
                                               int r0, int ntp0, int lane, float acc[8][4]) {
    int g = lane >> 2, tig = lane & 3;
    const uint32_t* ua0 = u_s + (r0 + g) * 132 + tig;
#pragma unroll
    for (int kstep = 0; kstep < 16; ++kstep) {
        uint32_t a0 = ua0[kstep * 8];
        uint32_t a1 = ua0[kstep * 8 + 8 * 132];
        uint32_t a2 = ua0[kstep * 8 + 4];
        uint32_t a3 = ua0[kstep * 8 + 8 * 132 + 4];
        const uint4* bp = Bf4 + (size_t)kstep * 512 + ntp0 * 32 + lane;
#pragma unroll
        for (int p = 0; p < 4; ++p) {
            uint4 b = __ldg(bp + p * 32);
            mma_bf16(acc[2 * p],     a0, a1, a2, a3, b.x, b.y);
            mma_bf16(acc[2 * p + 1], a0, a1, a2, a3, b.z, b.w);
        }
    }
}

// ================= node GEMM (split-N: gridDim.x = 2 * ceil(M/64)) =================
__global__ __launch_bounds__(256, 3) void node_mma(
    const float* __restrict__ A1, const uint4* __restrict__ B1f,
    const float* __restrict__ A2, const uint4* __restrict__ B2f,
    const float* __restrict__ bias, const float* __restrict__ resid,
    float* __restrict__ C, int M, int act) {
    __shared__ uint32_t u_s[64 * 132];
    int tid = threadIdx.x, wid = tid >> 5, lane = tid & 31;
    int m0 = (blockIdx.x >> 1) * 64;
    int bch = blockIdx.x & 1;
    int r0 = (wid >> 1) * 16;
    int ntp0 = bch * 8 + (wid & 1) * 4;

    float acc[8][4] = {};
    int npass = A2 ? 2 : 1;
    for (int pass = 0; pass < npass; ++pass) {
        const float* A = pass ? A2 : A1;
        const uint4* Bf = pass ? B2f : B1f;
        __syncthreads();
#pragma unroll 4
        for (int it = 0; it < 16; ++it) {
            int idx = it * 256 + tid;
            int e = idx >> 6;
            int kq = (idx & 63) << 2;
            int row = min(m0 + e, M - 1);
            float4 v = *(const float4*)&A[(size_t)row * H + kq];
            uint2 w;
            w.x = pack2(v.x, v.y);
            w.y = pack2(v.z, v.w);
            *(uint2*)&u_s[e * 132 + (kq >> 1)] = w;
        }
        __syncthreads();
        mma_block_half(u_s, Bf, r0, ntp0, lane, acc);
    }

    int g = lane >> 2, tig = lane & 3;
    int row0 = m0 + r0 + g, row1 = row0 + 8;
#pragma unroll
    for (int j = 0; j < 8; ++j) {
        int col = (ntp0 * 2 + j) * 8 + 2 * tig;
        float b0v = 0.f, b1v = 0.f;
        if (bias) { b0v = bias[col]; b1v = bias[col + 1]; }
        float v00 = acc[j][0] + b0v, v01 = acc[j][1] + b1v;
        float v10 = acc[j][2] + b0v, v11 = acc[j][3] + b1v;
        if (act) { v00 = siluf(v00); v01 = siluf(v01); v10 = siluf(v10); v11 = siluf(v11); }
        if (row0 < M) {
            if (resid) {
                float2 rv = *(const float2*)&resid[(size_t)row0 * H + col];
                v00 += rv.x; v01 += rv.y;
            }
            *(float2*)&C[(size_t)row0 * H + col] = make_float2(v00, v01);
        }
        if (row1 < M) {
            if (resid) {
                float2 rv = *(const float2*)&resid[(size_t)row1 * H + col];
                v10 += rv.x; v11 += rv.y;
            }
            *(float2*)&C[(size_t)row1 * H + col] = make_float2(v10, v11);
        }
    }
}

// ================= dual projection (split-N) =================
__global__ __launch_bounds__(256, 3) void dual_proj(
    const float* __restrict__ A, const uint4* __restrict__ B1f, const uint4* __restrict__ B2f,
    float* __restrict__ O1, float* __restrict__ O2, int M) {
    __shared__ uint32_t u_s[64 * 132];
    int tid = threadIdx.x, wid = tid >> 5, lane = tid & 31;
    int m0 = (blockIdx.x >> 1) * 64;
    int bch = blockIdx.x & 1;
    int r0 = (wid >> 1) * 16;
    int ntp0 = bch * 8 + (wid & 1) * 4;
    int g = lane >> 2, tig = lane & 3;

#pragma unroll 4
    for (int it = 0; it < 16; ++it) {
        int idx = it * 256 + tid;
        int e = idx >> 6;
        int kq = (idx & 63) << 2;
        int row = min(m0 + e, M - 1);
        float4 v = *(const float4*)&A[(size_t)row * H + kq];
        uint2 w;
        w.x = pack2(v.x, v.y);
        w.y = pack2(v.z, v.w);
        *(uint2*)&u_s[e * 132 + (kq >> 1)] = w;
    }
    __syncthreads();

    int row0 = m0 + r0 + g, row1 = row0 + 8;
#pragma unroll
    for (int pass = 0; pass < 2; ++pass) {
        const uint4* Bf = pass ? B2f : B1f;
        float* O = pass ? O2 : O1;
        float acc[8][4] = {};
        mma_block_half(u_s, Bf, r0, ntp0, lane, acc);
#pragma unroll
        for (int j = 0; j < 8; ++j) {
            int col = (ntp0 * 2 + j) * 8 + 2 * tig;
            if (row0 < M) *(float2*)&O[(size_t)row0 * H + col] = make_float2(acc[j][0], acc[j][1]);
            if (row1 < M) *(float2*)&O[(size_t)row1 * H + col] = make_float2(acc[j][2], acc[j][3]);
        }
    }
}

// ================= edge kernel: R15 structure (2 CTAs/SM) + v4 reductions =================
// smem (u32 units)
#define EU   0
#define EPS  8448
#define EATT 8512
#define EB2  8576
#define EWV  8832
#define ESR  9088
#define ESC  9152
#define EEA  9216
#define ETOT 9344
#define EDGE_SMEM (ETOT * 4)

template <bool COORD>
__global__ __launch_bounds__(256, 2) void edge_bf16_kernel(
    const float* __restrict__ Pa, const float* __restrict__ Pb,
    const float* __restrict__ wtail, const float* __restrict__ b1,
    const uint4* __restrict__ W2F, const float* __restrict__ b2,
    const float* __restrict__ wv, const float* __restrict__ ab,
    float* __restrict__ agg, const float* __restrict__ xg) {
    extern __shared__ uint32_t sm32[];
    float* ps    = (float*)(sm32 + EPS);
    float* att_s = (float*)(sm32 + EATT);
    float* b2s   = (float*)(sm32 + EB2);
    float* wvs   = (float*)(sm32 + EWV);
    int* srow_s  = (int*)(sm32 + ESR);
    int* scol_s  = (int*)(sm32 + ESC);
    float* eas   = (float*)(sm32 + EEA);

    int tid = threadIdx.x, wid = tid >> 5, lane = tid & 31;
    int g = lane >> 2, tig = lane & 3;
    int e0 = blockIdx.x * 64;
    int rg = wid >> 2;
    int cq = wid & 3;

    if (tid < 64) {
        srow_s[tid] = g_srow[e0 + tid];
        scol_s[tid] = g_scol[e0 + tid];
        float2 a = g_sea[e0 + tid];
        eas[tid] = a.x;
        eas[64 + tid] = a.y;
        ps[tid] = 0.f;
    }
    b2s[tid] = b2[tid];
    wvs[tid] = wv[tid];

    int kq = (tid & 63) << 2;
    float4 w0 = *(const float4*)&wtail[kq];
    float4 w1 = *(const float4*)&wtail[H + kq];
    float4 bv = *(const float4*)&b1[kq];
    __syncthreads();

    int esub = tid >> 6;
#pragma unroll 4
    for (int it = 0; it < 16; ++it) {
        int e = it * 4 + esub;
        int r = srow_s[e], cl = scol_s[e];
        float4 pa = *(const float4*)&Pa[(size_t)r * H + kq];
        float4 pb = *(const float4*)&Pb[(size_t)cl * H + kq];
        float a0 = eas[e], a1 = eas[64 + e];
        float t0 = siluf(pa.x + pb.x + a0 * w0.x + a1 * w1.x + bv.x);
        float t1 = siluf(pa.y + pb.y + a0 * w0.y + a1 * w1.y + bv.y);
        float t2 = siluf(pa.z + pb.z + a0 * w0.z + a1 * w1.z + bv.z);
        float t3 = siluf(pa.w + pb.w + a0 * w0.w + a1 * w1.w + bv.w);
        uint2 w;
        w.x = pack2(t0, t1);
        w.y = pack2(t2, t3);
        *(uint2*)&sm32[EU + e * 132 + (kq >> 1)] = w;
    }
    __syncthreads();

    float acc[2][8][4] = {};
    {
        const uint32_t* ua_base = sm32 + EU + (rg * 32 + g) * 132 + tig;
#pragma unroll
        for (int kstep = 0; kstep < 16; ++kstep) {
            uint32_t a[2][4];
#pragma unroll
            for (int s = 0; s < 2; ++s) {
                const uint32_t* ua = ua_base + s * 16 * 132 + kstep * 8;
                a[s][0] = ua[0];
                a[s][1] = ua[8 * 132];
                a[s][2] = ua[4];
                a[s][3] = ua[8 * 132 + 4];
            }
            const uint4* bp = W2F + (size_t)kstep * 512 + cq * 128 + lane;
#pragma unroll
            for (int p = 0; p < 4; ++p) {
                uint4 b = __ldg(bp + p * 32);
#pragma unroll
                for (int s = 0; s < 2; ++s) {
                    mma_bf16(acc[s][2 * p],     a[s][0], a[s][1], a[s][2], a[s][3], b.x, b.y);
                    mma_bf16(acc[s][2 * p + 1], a[s][0], a[s][1], a[s][2], a[s][3], b.z, b.w);
                }
            }
        }
    }
    __syncthreads();

#pragma unroll
    for (int s = 0; s < 2; ++s) {
        int row0 = rg * 32 + s * 16 + g, row1 = row0 + 8;
        float p0 = 0.f, p1 = 0.f;
#pragma unroll
        for (int nt = 0; nt < 8; ++nt) {
            int col = cq * 64 + nt * 8 + 2 * tig;
            float bb0 = b2s[col], bb1 = b2s[col + 1];
            float wc0 = wvs[col], wc1 = wvs[col + 1];
            float v00 = siluf(acc[s][nt][0] + bb0), v01 = siluf(acc[s][nt][1] + bb1);
            float v10 = siluf(acc[s][nt][2] + bb0), v11 = siluf(acc[s][nt][3] + bb1);
            if (!COORD) {
                sm32[EU + row0 * 132 + (cq * 8 + nt) * 4 + tig] = pack2(v00, v01);
                sm32[EU + row1 * 132 + (cq * 8 + nt) * 4 + tig] = pack2(v10, v11);
            }
            p0 += v00 * wc0 + v01 * wc1;
            p1 += v10 * wc0 + v11 * wc1;
        }
        atomicAdd(&ps[row0], p0);
        atomicAdd(&ps[row1], p1);
    }
    __syncthreads();

    if (COORD) {
        if (tid < 64) {
            float phi = ps[tid] * 0.01f;
            int r = srow_s[tid], c = scol_s[tid];
            float dx = xg[r * 3 + 0] - xg[c * 3 + 0];
            float dy = xg[r * 3 + 1] - xg[c * 3 + 1];
            float dz = xg[r * 3 + 2] - xg[c * 3 + 2];
            float inv = 1.0f / (sqrtf(dx * dx + dy * dy + dz * dz + 1e-8f) + 1.0f);
            atomicAdd(&agg[(size_t)r * 3 + 0], dx * inv * phi);
            atomicAdd(&agg[(size_t)r * 3 + 1], dy * inv * phi);
            atomicAdd(&agg[(size_t)r * 3 + 2], dz * inv * phi);
        }
    } else {
        if (tid < 64) att_s[tid] = sigmf(ps[tid] + ab[0]) * 0.01f;
        __syncthreads();
        // segmented reduction over sorted rows; flushes use vector RED (2x v4 per 8 cols)
        int cch = tid & 31;
        int s0 = (tid >> 5) * 8;
        float av[8] = {};
        int currow = srow_s[s0];
        for (int s = s0; s < s0 + 8; ++s) {
            int r = srow_s[s];
            if (r != currow) {
                float* dst = agg + (size_t)currow * H + cch * 8;
                red_add_v4(dst,     av[0], av[1], av[2], av[3]);
                red_add_v4(dst + 4, av[4], av[5], av[6], av[7]);
#pragma unroll
                for (int j = 0; j < 8; ++j) av[j] = 0.f;
                currow = r;
            }
            float a = att_s[s];
            uint4 w4 = *(const uint4*)(sm32 + EU + s * 132 + cch * 4);
            float2 f;
            f = up2(w4.x); av[0] += f.x * a; av[1] += f.y * a;
            f = up2(w4.y); av[2] += f.x * a; av[3] += f.y * a;
            f = up2(w4.z); av[4] += f.x * a; av[5] += f.y * a;
            f = up2(w4.w); av[6] += f.x * a; av[7] += f.y * a;
        }
        float* dst = agg + (size_t)currow * H + cch * 8;
        red_add_v4(dst,     av[0], av[1], av[2], av[3]);
        red_add_v4(dst + 4, av[4], av[5], av[6], av[7]);
    }
}

__global__ void x_final_kernel(const float* __restrict__ x, const float* __restrict__ aggx,
                               float* __restrict__ out) {
    int i = blockIdx.x * blockDim.x + threadIdx.x;
    if (i < NN * 3) out[i] = x[i] + aggx[i];
}

// ================= launch =================
extern "C" void kernel_launch(void* const* d_in, const int* in_sizes, int n_in,
                              void* d_out, int out_size) {
    const float* h0 = (const float*)d_in[0];
    const float* x = (const float*)d_in[1];
    const int* ei = (const int*)d_in[2];
    const float* ea = (const float*)d_in[3];
    const float* p[2][10];
    for (int l = 0; l < 2; ++l)
        for (int i = 0; i < 10; ++i) p[l][i] = (const float*)d_in[4 + l * 10 + i];
    // p[l]: 0 ew1, 1 eb1, 2 ew2, 3 eb2, 4 nw1, 5 nb1, 6 nw2, 7 nb2, 8 aw, 9 ab
    const float* cw1 = (const float*)d_in[24];
    const float* cb1 = (const float*)d_in[25];
    const float* cw2 = (const float*)d_in[26];
    const float* cb2 = (const float*)d_in[27];
    const float* cw3 = (const float*)d_in[28];

    float* outh = (float*)d_out;
    float* outx = outh + (size_t)NN * H;

    float *Pa, *Pb, *agg2, *q, *h1, *aggx;
    unsigned* wf;
    cudaGetSymbolAddress((void**)&Pa, g_Pa);
    cudaGetSymbolAddress((void**)&Pb, g_Pb);
    cudaGetSymbolAddress((void**)&agg2, g_agg2);
    cudaGetSymbolAddress((void**)&q, g_q);
    cudaGetSymbolAddress((void**)&h1, g_h1);
    cudaGetSymbolAddress((void**)&aggx, g_aggx);
    cudaGetSymbolAddress((void**)&wf, g_WF);

    cudaFuncSetAttribute(edge_bf16_kernel<false>, cudaFuncAttributeMaxDynamicSharedMemorySize, EDGE_SMEM);
    cudaFuncSetAttribute(edge_bf16_kernel<true>, cudaFuncAttributeMaxDynamicSharedMemorySize, EDGE_SMEM);

    int gnode = 2 * ((NN + 63) / 64);   // split-N: 2 blocks per 64-row tile (R15 proven)

    WPtrs wp;
    for (int l = 0; l < 2; ++l) {
        wp.w[l * 6 + 0] = p[l][0];
        wp.w[l * 6 + 1] = p[l][0] + 256 * H;
        wp.w[l * 6 + 2] = p[l][2];
        wp.w[l * 6 + 3] = p[l][4];
        wp.w[l * 6 + 4] = p[l][4] + 256 * H;
        wp.w[l * 6 + 5] = p[l][6];
    }
    wp.w[12] = cw1;
    wp.w[13] = cw1 + 256 * H;
    wp.w[14] = cw2;
    combo_prep<<<1920, 256>>>(wp, ei);
    scan_kernel<<<1, 256>>>();
    scatter_kernel<<<(NE + 255) / 256, 256>>>(ei, ea);

    const uint4* WF = (const uint4*)wf;
#define WFM(m) (WF + (size_t)(m) * 8192)

    const float* hcur = h0;
    float* houts[2] = {h1, outh};
    for (int l = 0; l < 2; ++l) {
        float* agg = agg2 + (size_t)l * NN * H;
        dual_proj<<<gnode, 256>>>(hcur, WFM(l * 6 + 0), WFM(l * 6 + 1), Pa, Pb, NN);
        edge_bf16_kernel<false><<<NE / 64, 256, EDGE_SMEM>>>(
            Pa, Pb, p[l][0] + 512 * H, p[l][1], WFM(l * 6 + 2), p[l][3], p[l][8], p[l][9],
            agg, nullptr);
        node_mma<<<gnode, 256>>>(hcur, WFM(l * 6 + 3), agg, WFM(l * 6 + 4),
                                 p[l][5], nullptr, q, NN, 1);
        node_mma<<<gnode, 256>>>(q, WFM(l * 6 + 5), nullptr, nullptr,
                                 p[l][7], hcur, houts[l], NN, 0);
        hcur = houts[l];
    }

    dual_proj<<<gnode, 256>>>(hcur, WFM(12), WFM(13), Pa, Pb, NN);
    edge_bf16_kernel<true><<<NE / 64, 256, EDGE_SMEM>>>(
        Pa, Pb, cw1 + 512 * H, cb1, WFM(14), cb2, cw3, nullptr, aggx, x);
    x_final_kernel<<<(NN * 3 + 255) / 256, 256>>>(x, aggx, outx);
}